// round 10
// baseline (speedup 1.0000x reference)
#include <cuda_runtime.h>
#include <cuda_fp16.h>
#include <cstdint>
#include <math.h>

#define NT   2048
#define DIM  2048
#define FFN_ 768
#define NE   64
#define TOPK 8
#define NP   (NT*TOPK)
#define CAP  512

#define STG     3
#define ASTG    16384                  // A: 128 rows x 64 k x 2B
#define BSTG    32768                  // B: 256 rows x 64 k x 2B
#define STAGEB  (ASTG + BSTG)          // 48KB
#define SMEM_DYN (STG * STAGEB)        // 144KB

// ---------------- scratch ----------------------------------------------------
__device__ int    g_cnt[NE];
__device__ int    g_tok[NE*CAP];
__device__ int    g_eid[NP];
__device__ int    g_slot[NP];
__device__ float  g_scr[NP];
__device__ __half g_xh[(size_t)NT*DIM];       // 8 MB fp16 tokens
__device__ __half g_h[(size_t)NE*CAP*FFN_];   // 50 MB fp16 activations
__device__ __half g_y[(size_t)NE*CAP*DIM];    // 134 MB fp16 expert outputs

// ---------------- helpers ----------------------------------------------------
__device__ __forceinline__ void ldsm4(uint32_t* r, uint32_t addr) {
    asm volatile("ldmatrix.sync.aligned.m8n8.x4.shared.b16 {%0,%1,%2,%3}, [%4];"
                 : "=r"(r[0]), "=r"(r[1]), "=r"(r[2]), "=r"(r[3]) : "r"(addr));
}
__device__ __forceinline__ void mma16816(float* d, const uint32_t* a, const uint32_t* b) {
    asm volatile("mma.sync.aligned.m16n8k16.row.col.f32.f16.f16.f32 "
                 "{%0,%1,%2,%3}, {%4,%5,%6,%7}, {%8,%9}, {%0,%1,%2,%3};"
                 : "+f"(d[0]), "+f"(d[1]), "+f"(d[2]), "+f"(d[3])
                 : "r"(a[0]), "r"(a[1]), "r"(a[2]), "r"(a[3]), "r"(b[0]), "r"(b[1]));
}
__device__ __forceinline__ uint32_t pack2(float a, float b) {
    __half2 h = __floats2half2_rn(a, b);
    return *reinterpret_cast<uint32_t*>(&h);
}
__device__ __forceinline__ uint4 pack8(const float4& u, const float4& v) {
    uint4 p; p.x = pack2(u.x, u.y); p.y = pack2(u.z, u.w);
    p.z = pack2(v.x, v.y); p.w = pack2(v.z, v.w);
    return p;
}
__device__ __forceinline__ float silu_(float g) { return g / (1.f + __expf(-g)); }

#define CP16(s, g) asm volatile("cp.async.cg.shared.global [%0], [%1], 16;" :: "r"(s), "l"(g))
#define CPCOMMIT() asm volatile("cp.async.commit_group;" ::: "memory")
#define CPWAIT1()  asm volatile("cp.async.wait_group 1;" ::: "memory")

// ---------------- K1: gating (fp32 exact) + x->fp16 --------------------------
__global__ __launch_bounds__(256) void k_gate(const float* __restrict__ x,
                                              const float* __restrict__ gw) {
    __shared__ float sx[4][DIM];
    __shared__ float slog[4][NE];
    const int t0 = blockIdx.x * 4;
    const int tid = threadIdx.x;
    for (int i = tid; i < 4 * (DIM / 4); i += 256) {
        int row = i / (DIM / 4), c = i % (DIM / 4);
        ((float4*)sx[row])[c] = ((const float4*)(x + (size_t)(t0 + row) * DIM))[c];
    }
    __syncthreads();
    const int warp = tid >> 5, lane = tid & 31;
    for (int d = warp * 32; d < warp * 32 + 32; d++) {
        int tk = d >> 6, e = d & 63;
        const float* w = gw + (size_t)e * DIM;
        float acc = 0.f;
        for (int i = lane * 4; i < DIM; i += 128) {
            float4 xv = *(const float4*)&sx[tk][i];
            float4 wv = *(const float4*)&w[i];
            acc += xv.x * wv.x + xv.y * wv.y + xv.z * wv.z + xv.w * wv.w;
        }
        #pragma unroll
        for (int o = 16; o; o >>= 1) acc += __shfl_xor_sync(0xffffffffu, acc, o);
        if (lane == 0) slog[tk][e] = acc;
    }
    #pragma unroll
    for (int i = 0; i < 4; i++) {
        int q = tid + 256 * i;
        int row = q >> 8, c = (q & 255) * 8;
        float4 u = *(const float4*)&sx[row][c];
        float4 v = *(const float4*)&sx[row][c + 4];
        *(uint4*)&g_xh[(size_t)(t0 + row) * DIM + c] = pack8(u, v);
    }
    __syncthreads();
    if (tid < 4) {
        const int tk = tid, token = t0 + tk;
        float m = -1e30f;
        for (int e = 0; e < NE; e++) m = fmaxf(m, slog[tk][e]);
        float pr[NE], s = 0.f;
        for (int e = 0; e < NE; e++) { pr[e] = __expf(slog[tk][e] - m); s += pr[e]; }
        const float inv = 1.f / s;
        for (int k = 0; k < TOPK; k++) {
            float best = -1.f; int be = 0;
            for (int e = 0; e < NE; e++) if (pr[e] > best) { best = pr[e]; be = e; }
            g_eid[token * TOPK + k] = be;
            g_scr[token * TOPK + k] = best * inv;
            pr[be] = -2.f;
        }
    }
}

// ---------------- K2: routing ------------------------------------------------
__global__ void k_zero() { if (threadIdx.x < NE) g_cnt[threadIdx.x] = 0; }
__global__ void k_route() {
    int p = blockIdx.x * 256 + threadIdx.x;
    if (p >= NP) return;
    int e = g_eid[p];
    int slot = atomicAdd(&g_cnt[e], 1);
    g_slot[p] = slot;
    if (slot < CAP) g_tok[e * CAP + slot] = p >> 3;
}

// ====== 128(M) x 256(N) fp16 MMA mainloop, 512 thr, 16 warps (2m x 8n) =======
// warp tile 64x32: acc[4][4][4] = 64 regs. B prefetch held PACKED (uint4[4]).
struct Frag { float a[4][4][4]; };

__device__ __forceinline__ void mainloop(
    uint8_t* sm, uint32_t sbase,
    const __half* (&asrc)[2], const float* (&bsrc)[4],
    uint32_t (&offa)[2], uint32_t (&offb)[4],
    int wm, int wn, int lane, int NK, Frag& F)
{
    #pragma unroll
    for (int a = 0; a < 4; a++)
        #pragma unroll
        for (int b = 0; b < 4; b++)
            #pragma unroll
            for (int c = 0; c < 4; c++) F.a[a][b][c] = 0.f;

    // prologue: A(0), A(1) via cp.async; B(0) direct packed STS; B(1) in regs
    #pragma unroll
    for (int s = 0; s < 2; s++) {
        #pragma unroll
        for (int i = 0; i < 2; i++)
            CP16(sbase + s * STAGEB + offa[i], asrc[i] + s * 64);
        CPCOMMIT();
    }
    #pragma unroll
    for (int i = 0; i < 4; i++) {
        float4 u = *(const float4*)(bsrc[i]);
        float4 v = *(const float4*)(bsrc[i] + 4);
        *(uint4*)(sm + ASTG + offb[i]) = pack8(u, v);
    }
    uint4 vb[4];
    #pragma unroll
    for (int i = 0; i < 4; i++) {
        float4 u = *(const float4*)(bsrc[i] + 64);
        float4 v = *(const float4*)(bsrc[i] + 68);
        vb[i] = pack8(u, v);
    }

    #pragma unroll 1
    for (int j = 0; j < NK; j++) {
        const int cur = j % STG, nxt = (j + 1) % STG, nx2 = (j + 2) % STG;
        CPWAIT1();
        __syncthreads();
        // issue A(j+2)
        if (j + 2 < NK) {
            #pragma unroll
            for (int i = 0; i < 2; i++)
                CP16(sbase + nx2 * STAGEB + offa[i], asrc[i] + (j + 2) * 64);
        }
        CPCOMMIT();
        // STS B(j+1) (already packed)
        if (j + 1 < NK) {
            #pragma unroll
            for (int i = 0; i < 4; i++)
                *(uint4*)(sm + nxt * STAGEB + ASTG + offb[i]) = vb[i];
        }
        // LDG+pack B(j+2)
        if (j + 2 < NK) {
            #pragma unroll
            for (int i = 0; i < 4; i++) {
                float4 u = *(const float4*)(bsrc[i] + (j + 2) * 64);
                float4 v = *(const float4*)(bsrc[i] + (j + 2) * 64 + 4);
                vb[i] = pack8(u, v);
            }
        }
        // MMA(j)
        const uint32_t sA = sbase + cur * STAGEB, sB = sA + ASTG;
        #pragma unroll
        for (int ks = 0; ks < 4; ks++) {
            uint32_t af[4][4], bf[2][4];
            #pragma unroll
            for (int mt = 0; mt < 4; mt++) {
                int row = wm * 64 + mt * 16 + (lane & 15);
                int byt = ks * 32 + ((lane >> 4) << 4);
                ldsm4(af[mt], sA + row * 128 + (byt ^ ((row & 7) << 4)));
            }
            #pragma unroll
            for (int n2 = 0; n2 < 2; n2++) {
                int row = wn * 32 + n2 * 16 + ((lane >> 4) << 3) + (lane & 7);
                int byt = ks * 32 + (((lane >> 3) & 1) << 4);
                ldsm4(bf[n2], sB + row * 128 + (byt ^ ((row & 7) << 4)));
            }
            #pragma unroll
            for (int mt = 0; mt < 4; mt++)
                #pragma unroll
                for (int nt = 0; nt < 4; nt++)
                    mma16816(F.a[mt][nt], af[mt], &bf[nt >> 1][(nt & 1) * 2]);
        }
    }
}

// ---------------- K3: gate/up GEMM + SwiGLU (N=256 <-> f-slab 128) -----------
__global__ __launch_bounds__(512, 1) void k_gateup_mma(const float* __restrict__ wg,
                                                       const float* __restrict__ wu) {
    extern __shared__ __align__(1024) uint8_t sm[];
    const int e = blockIdx.z;
    int nrows = g_cnt[e]; if (nrows > CAP) nrows = CAP;
    const int row0 = blockIdx.y * 128;
    if (row0 >= nrows) return;
    const int f0 = blockIdx.x * 128;

    const int tid = threadIdx.x;
    const int wid = tid >> 5, lane = tid & 31;
    const int wm = wid & 1, wn = wid >> 1;
    uint32_t sbase;
    asm("{ .reg .u64 t; cvta.to.shared.u64 t, %1; cvt.u32.u64 %0, t; }" : "=r"(sbase) : "l"(sm));

    const __half* asrc[2]; const float* bsrc[4];
    uint32_t offa[2], offb[4];
    #pragma unroll
    for (int i = 0; i < 2; i++) {
        int q = tid + 512 * i;            // 1024 A units
        int r = q >> 3, c = q & 7;
        int rr = row0 + r;
        int tok = g_tok[e * CAP + (rr < nrows ? rr : 0)];
        asrc[i] = g_xh + (size_t)tok * DIM + c * 8;
        offa[i] = r * 128 + ((c * 16) ^ ((r & 7) << 4));
    }
    #pragma unroll
    for (int i = 0; i < 4; i++) {
        int q = tid + 512 * i;            // 2048 B units
        int r = q >> 3, c = q & 7;        // B row r in [0,256)
        int t8 = r >> 3, w8 = r & 7;      // even t8 = gate, odd = up
        int fr = f0 + (t8 >> 1) * 8 + w8;
        const float* wb = (t8 & 1) ? wu : wg;
        bsrc[i] = wb + ((size_t)e * FFN_ + fr) * DIM + c * 8;
        offb[i] = r * 128 + ((c * 16) ^ ((r & 7) << 4));
    }

    Frag F;
    mainloop(sm, sbase, asrc, bsrc, offa, offb, wm, wn, lane, DIM / 64, F);

    const int qrow = lane >> 2, qcol = (lane & 3) * 2;
    #pragma unroll
    for (int mt = 0; mt < 4; mt++) {
        int mbase = row0 + wm * 64 + mt * 16;
        #pragma unroll
        for (int p = 0; p < 2; p++) {
            int fbase = f0 + (wn * 2 + p) * 8 + qcol;
            float* gA = F.a[mt][2 * p];
            float* uA = F.a[mt][2 * p + 1];
            int r0 = mbase + qrow, r1 = mbase + qrow + 8;
            if (r0 < nrows) {
                __half2 h = __floats2half2_rn(silu_(gA[0]) * uA[0], silu_(gA[1]) * uA[1]);
                *(__half2*)&g_h[((size_t)e * CAP + r0) * FFN_ + fbase] = h;
            }
            if (r1 < nrows) {
                __half2 h = __floats2half2_rn(silu_(gA[2]) * uA[2], silu_(gA[3]) * uA[3]);
                *(__half2*)&g_h[((size_t)e * CAP + r1) * FFN_ + fbase] = h;
            }
        }
    }
}

// ---------------- K4: down GEMM (N=256) --------------------------------------
__global__ __launch_bounds__(512, 1) void k_down_mma(const float* __restrict__ wd) {
    extern __shared__ __align__(1024) uint8_t sm[];
    const int e = blockIdx.z;
    int nrows = g_cnt[e]; if (nrows > CAP) nrows = CAP;
    const int row0 = blockIdx.y * 128;
    if (row0 >= nrows) return;
    const int d0 = blockIdx.x * 256;

    const int tid = threadIdx.x;
    const int wid = tid >> 5, lane = tid & 31;
    const int wm = wid & 1, wn = wid >> 1;
    uint32_t sbase;
    asm("{ .reg .u64 t; cvta.to.shared.u64 t, %1; cvt.u32.u64 %0, t; }" : "=r"(sbase) : "l"(sm));

    const __half* asrc[2]; const float* bsrc[4];
    uint32_t offa[2], offb[4];
    #pragma unroll
    for (int i = 0; i < 2; i++) {
        int q = tid + 512 * i;
        int r = q >> 3, c = q & 7;
        asrc[i] = g_h + ((size_t)e * CAP + row0 + r) * FFN_ + c * 8;
        offa[i] = r * 128 + ((c * 16) ^ ((r & 7) << 4));
    }
    #pragma unroll
    for (int i = 0; i < 4; i++) {
        int q = tid + 512 * i;
        int r = q >> 3, c = q & 7;
        bsrc[i] = wd + ((size_t)e * DIM + d0 + r) * FFN_ + c * 8;
        offb[i] = r * 128 + ((c * 16) ^ ((r & 7) << 4));
    }

    Frag F;
    mainloop(sm, sbase, asrc, bsrc, offa, offb, wm, wn, lane, FFN_ / 64, F);

    const int qrow = lane >> 2, qcol = (lane & 3) * 2;
    #pragma unroll
    for (int mt = 0; mt < 4; mt++) {
        int mbase = row0 + wm * 64 + mt * 16;
        #pragma unroll
        for (int nt = 0; nt < 4; nt++) {
            int dcol = d0 + wn * 32 + nt * 8 + qcol;
            int r0 = mbase + qrow, r1 = mbase + qrow + 8;
            if (r0 < nrows) {
                __half2 h = __floats2half2_rn(F.a[mt][nt][0], F.a[mt][nt][1]);
                *(__half2*)&g_y[((size_t)e * CAP + r0) * DIM + dcol] = h;
            }
            if (r1 < nrows) {
                __half2 h = __floats2half2_rn(F.a[mt][nt][2], F.a[mt][nt][3]);
                *(__half2*)&g_y[((size_t)e * CAP + r1) * DIM + dcol] = h;
            }
        }
    }
}

// ---------------- K5: weighted combine (fp16 y, fp32 acc) --------------------
__global__ __launch_bounds__(256) void k_combine(float* __restrict__ out) {
    const int t = blockIdx.x;
    const int tid = threadIdx.x;
    float acc[8];
    #pragma unroll
    for (int i = 0; i < 8; i++) acc[i] = 0.f;
    #pragma unroll
    for (int k = 0; k < TOPK; k++) {
        const int p = t * TOPK + k;
        const int e = g_eid[p];
        const int s = g_slot[p];
        if (s >= CAP) continue;
        const float sc = g_scr[p];
        const uint4* yr = (const uint4*)&g_y[((size_t)e * CAP + s) * DIM];
        uint4 v = yr[tid];
        uint32_t w[4] = {v.x, v.y, v.z, v.w};
        #pragma unroll
        for (int i = 0; i < 4; i++) {
            float2 f = __half22float2(*(__half2*)&w[i]);
            acc[2*i]   += sc * f.x;
            acc[2*i+1] += sc * f.y;
        }
    }
    float* op = out + (size_t)t * DIM + tid * 8;
    *(float4*)op       = make_float4(acc[0], acc[1], acc[2], acc[3]);
    *(float4*)(op + 4) = make_float4(acc[4], acc[5], acc[6], acc[7]);
}

// ---------------- launch -----------------------------------------------------
extern "C" void kernel_launch(void* const* d_in, const int* in_sizes, int n_in,
                              void* d_out, int out_size) {
    (void)in_sizes; (void)n_in; (void)out_size;
    const float* x      = (const float*)d_in[0];
    const float* gate_w = (const float*)d_in[1];
    const float* w_gate = (const float*)d_in[2];
    const float* w_up   = (const float*)d_in[3];
    const float* w_down = (const float*)d_in[4];
    float* out          = (float*)d_out;

    cudaFuncSetAttribute(k_gateup_mma, cudaFuncAttributeMaxDynamicSharedMemorySize, SMEM_DYN);
    cudaFuncSetAttribute(k_down_mma,   cudaFuncAttributeMaxDynamicSharedMemorySize, SMEM_DYN);

    k_gate<<<NT / 4, 256>>>(x, gate_w);
    k_zero<<<1, 64>>>();
    k_route<<<NP / 256, 256>>>();
    k_gateup_mma<<<dim3(FFN_ / 128, CAP / 128, NE), 512, SMEM_DYN>>>(w_gate, w_up);
    k_down_mma<<<dim3(DIM / 256, CAP / 128, NE), 512, SMEM_DYN>>>(w_down);
    k_combine<<<NT, 256>>>(out);
}

// round 11
// speedup vs baseline: 1.3017x; 1.3017x over previous
#include <cuda_runtime.h>
#include <cuda_fp16.h>
#include <cstdint>
#include <math.h>

#define NT   2048
#define DIM  2048
#define FFN_ 768
#define NE   64
#define TOPK 8
#define NP   (NT*TOPK)
#define CAP  512

#define STAGEB 32768                   // A 16KB + B 16KB (128 rows x 64 k fp16)
#define SMEM_DYN (2*STAGEB)            // double buffer, 64KB/CTA -> 2 CTAs/SM

// ---------------- scratch ----------------------------------------------------
__device__ int    g_cnt[NE];
__device__ int    g_tok[NE*CAP];
__device__ int    g_eid[NP];
__device__ int    g_slot[NP];
__device__ float  g_scr[NP];
__device__ __half g_xh[(size_t)NT*DIM];       // 8 MB fp16 tokens
__device__ __half g_h[(size_t)NE*CAP*FFN_];   // 50 MB fp16 activations
__device__ __half g_y[(size_t)NE*CAP*DIM];    // 134 MB fp16 expert outputs

// ---------------- helpers ----------------------------------------------------
__device__ __forceinline__ uint32_t smem_u32(const void* p) {
    uint32_t a;
    asm("{ .reg .u64 t; cvta.to.shared.u64 t, %1; cvt.u32.u64 %0, t; }" : "=r"(a) : "l"(p));
    return a;
}
__device__ __forceinline__ void ldsm4(uint32_t* r, uint32_t addr) {
    asm volatile("ldmatrix.sync.aligned.m8n8.x4.shared.b16 {%0,%1,%2,%3}, [%4];"
                 : "=r"(r[0]), "=r"(r[1]), "=r"(r[2]), "=r"(r[3]) : "r"(addr));
}
__device__ __forceinline__ void mma16816(float* d, const uint32_t* a, const uint32_t* b) {
    asm volatile("mma.sync.aligned.m16n8k16.row.col.f32.f16.f16.f32 "
                 "{%0,%1,%2,%3}, {%4,%5,%6,%7}, {%8,%9}, {%0,%1,%2,%3};"
                 : "+f"(d[0]), "+f"(d[1]), "+f"(d[2]), "+f"(d[3])
                 : "r"(a[0]), "r"(a[1]), "r"(a[2]), "r"(a[3]), "r"(b[0]), "r"(b[1]));
}
__device__ __forceinline__ uint32_t pack2(float a, float b) {
    __half2 h = __floats2half2_rn(a, b);
    return *reinterpret_cast<uint32_t*>(&h);
}
__device__ __forceinline__ uint4 pack8(const float4& u, const float4& v) {
    uint4 p; p.x = pack2(u.x, u.y); p.y = pack2(u.z, u.w);
    p.z = pack2(v.x, v.y); p.w = pack2(v.z, v.w);
    return p;
}
__device__ __forceinline__ float silu_(float g) { return g / (1.f + __expf(-g)); }

#define CP16(s, g) asm volatile("cp.async.cg.shared.global [%0], [%1], 16;" :: "r"(s), "l"(g))
#define CPCOMMIT() asm volatile("cp.async.commit_group;" ::: "memory")
#define CPWAIT0()  asm volatile("cp.async.wait_group 0;" ::: "memory")

// ---------------- K1: gating (fp32 exact) + x->fp16 --------------------------
__global__ __launch_bounds__(256) void k_gate(const float* __restrict__ x,
                                              const float* __restrict__ gw) {
    __shared__ float sx[4][DIM];
    __shared__ float slog[4][NE];
    const int t0 = blockIdx.x * 4;
    const int tid = threadIdx.x;
    for (int i = tid; i < 4 * (DIM / 4); i += 256) {
        int row = i / (DIM / 4), c = i % (DIM / 4);
        ((float4*)sx[row])[c] = ((const float4*)(x + (size_t)(t0 + row) * DIM))[c];
    }
    __syncthreads();
    const int warp = tid >> 5, lane = tid & 31;
    for (int d = warp * 32; d < warp * 32 + 32; d++) {
        int tk = d >> 6, e = d & 63;
        const float* w = gw + (size_t)e * DIM;
        float acc = 0.f;
        for (int i = lane * 4; i < DIM; i += 128) {
            float4 xv = *(const float4*)&sx[tk][i];
            float4 wv = *(const float4*)&w[i];
            acc += xv.x * wv.x + xv.y * wv.y + xv.z * wv.z + xv.w * wv.w;
        }
        #pragma unroll
        for (int o = 16; o; o >>= 1) acc += __shfl_xor_sync(0xffffffffu, acc, o);
        if (lane == 0) slog[tk][e] = acc;
    }
    #pragma unroll
    for (int i = 0; i < 4; i++) {
        int q = tid + 256 * i;
        int row = q >> 8, c = (q & 255) * 8;
        float4 u = *(const float4*)&sx[row][c];
        float4 v = *(const float4*)&sx[row][c + 4];
        *(uint4*)&g_xh[(size_t)(t0 + row) * DIM + c] = pack8(u, v);
    }
    __syncthreads();
    if (tid < 4) {
        const int tk = tid, token = t0 + tk;
        float m = -1e30f;
        for (int e = 0; e < NE; e++) m = fmaxf(m, slog[tk][e]);
        float pr[NE], s = 0.f;
        for (int e = 0; e < NE; e++) { pr[e] = __expf(slog[tk][e] - m); s += pr[e]; }
        const float inv = 1.f / s;
        for (int k = 0; k < TOPK; k++) {
            float best = -1.f; int be = 0;
            for (int e = 0; e < NE; e++) if (pr[e] > best) { best = pr[e]; be = e; }
            g_eid[token * TOPK + k] = be;
            g_scr[token * TOPK + k] = best * inv;
            pr[be] = -2.f;
        }
    }
}

// ---------------- K2: routing ------------------------------------------------
__global__ void k_zero() { if (threadIdx.x < NE) g_cnt[threadIdx.x] = 0; }
__global__ void k_route() {
    int p = blockIdx.x * 256 + threadIdx.x;
    if (p >= NP) return;
    int e = g_eid[p];
    int slot = atomicAdd(&g_cnt[e], 1);
    g_slot[p] = slot;
    if (slot < CAP) g_tok[e * CAP + slot] = p >> 3;
}

// == 128x128 fp16 MMA mainloop: 256 thr, 8 warps (2m x 4n), 64x32 warp tile ==
// Double-buffered (2 stages). A via cp.async (0 prefetch regs), B via
// LDG->pack->regs(uint4)->STS. Per-thread unit i: row r0+32i, col c (16B).
__device__ __forceinline__ void mainloop(
    uint8_t* sm, uint32_t sbase,
    const __half* const (&aptr)[4],           // gmem A row ptrs (+c*8), unit i
    const float* bsrc, int64_t bstride,       // B base (+c*8); unit i at +i*bstride
    uint32_t offa0,                           // smem offset of unit 0 (swizzled)
    int wm, int wn, int lane, int NK, float (&acc)[4][4][4])
{
    #pragma unroll
    for (int a = 0; a < 4; a++)
        #pragma unroll
        for (int b = 0; b < 4; b++)
            #pragma unroll
            for (int c = 0; c < 4; c++) acc[a][b][c] = 0.f;

    // prologue: A(0) cp.async; B(0) LDG+pack+STS; B(1) -> regs
    #pragma unroll
    for (int i = 0; i < 4; i++)
        CP16(sbase + offa0 + i * 4096, aptr[i]);
    CPCOMMIT();
    #pragma unroll
    for (int i = 0; i < 4; i++) {
        float4 u = *(const float4*)(bsrc + i * bstride);
        float4 v = *(const float4*)(bsrc + i * bstride + 4);
        *(uint4*)(sm + 16384 + offa0 + i * 4096) = pack8(u, v);
    }
    uint4 vb[4];
    #pragma unroll
    for (int i = 0; i < 4; i++) {
        float4 u = *(const float4*)(bsrc + i * bstride + 64);
        float4 v = *(const float4*)(bsrc + i * bstride + 68);
        vb[i] = pack8(u, v);
    }

    #pragma unroll 1
    for (int j = 0; j < NK; j++) {
        const uint32_t cur = (j & 1) * STAGEB, nxt = ((j + 1) & 1) * STAGEB;
        CPWAIT0();
        __syncthreads();
        // A(j+1) cp.async into other stage
        if (j + 1 < NK) {
            #pragma unroll
            for (int i = 0; i < 4; i++)
                CP16(sbase + nxt + offa0 + i * 4096, aptr[i] + (j + 1) * 64);
        }
        CPCOMMIT();
        // STS B(j+1) (pre-packed)
        if (j + 1 < NK) {
            #pragma unroll
            for (int i = 0; i < 4; i++)
                *(uint4*)(sm + nxt + 16384 + offa0 + i * 4096) = vb[i];
        }
        // LDG+pack B(j+2)
        if (j + 2 < NK) {
            #pragma unroll
            for (int i = 0; i < 4; i++) {
                float4 u = *(const float4*)(bsrc + i * bstride + (j + 2) * 64);
                float4 v = *(const float4*)(bsrc + i * bstride + (j + 2) * 64 + 4);
                vb[i] = pack8(u, v);
            }
        }
        // MMA(j)
        const uint32_t sA = sbase + cur, sB = sA + 16384;
        #pragma unroll
        for (int ks = 0; ks < 4; ks++) {
            uint32_t af[4][4], bf[2][4];
            #pragma unroll
            for (int mt = 0; mt < 4; mt++) {
                int row = wm * 64 + mt * 16 + (lane & 15);
                int byt = ks * 32 + ((lane >> 4) << 4);
                ldsm4(af[mt], sA + row * 128 + (byt ^ ((row & 7) << 4)));
            }
            #pragma unroll
            for (int n2 = 0; n2 < 2; n2++) {
                int row = wn * 32 + n2 * 16 + ((lane >> 4) << 3) + (lane & 7);
                int byt = ks * 32 + (((lane >> 3) & 1) << 4);
                ldsm4(bf[n2], sB + row * 128 + (byt ^ ((row & 7) << 4)));
            }
            #pragma unroll
            for (int mt = 0; mt < 4; mt++)
                #pragma unroll
                for (int nt = 0; nt < 4; nt++)
                    mma16816(acc[mt][nt], af[mt], &bf[nt >> 1][(nt & 1) * 2]);
        }
    }
}

// ---------------- K3: gate/up GEMM + SwiGLU ----------------------------------
__global__ __launch_bounds__(256, 2) void k_gateup_mma(const float* __restrict__ wg,
                                                       const float* __restrict__ wu) {
    extern __shared__ __align__(1024) uint8_t sm[];
    const int e = blockIdx.z;
    int nrows = g_cnt[e]; if (nrows > CAP) nrows = CAP;
    const int row0 = blockIdx.y * 128;
    if (row0 >= nrows) return;
    const int f0 = blockIdx.x * 64;

    const int tid = threadIdx.x;
    const int wid = tid >> 5, lane = tid & 31;
    const int wm = wid & 1, wn = wid >> 1;
    const uint32_t sbase = smem_u32(sm);

    const int r0 = tid >> 3, c = tid & 7;
    const uint32_t offa0 = r0 * 128 + ((c * 16) ^ ((r0 & 7) << 4));

    // A: 4 gathered token rows (r0 + 32i)
    const __half* aptr[4];
    #pragma unroll
    for (int i = 0; i < 4; i++) {
        int rr = row0 + r0 + 32 * i;
        int tok = g_tok[e * CAP + (rr < nrows ? rr : 0)];
        aptr[i] = g_xh + (size_t)tok * DIM + c * 8;
    }
    // B: row r0 -> tile t8=r0>>3 (even=gate, odd=up); +32 rows -> fr += 16
    const int t8 = r0 >> 3, w8 = r0 & 7;
    const int fr = f0 + (t8 >> 1) * 8 + w8;
    const float* wb = (t8 & 1) ? wu : wg;
    const float* bsrc = wb + ((size_t)e * FFN_ + fr) * DIM + c * 8;
    const int64_t bstride = (int64_t)16 * DIM;

    float acc[4][4][4];
    mainloop(sm, sbase, aptr, bsrc, bstride, offa0, wm, wn, lane, DIM / 64, acc);

    const int qrow = lane >> 2, qcol = (lane & 3) * 2;
    #pragma unroll
    for (int mt = 0; mt < 4; mt++) {
        int mbase = row0 + wm * 64 + mt * 16;
        #pragma unroll
        for (int p = 0; p < 2; p++) {
            int fbase = f0 + (wn * 2 + p) * 8 + qcol;
            float* gA = acc[mt][2 * p];
            float* uA = acc[mt][2 * p + 1];
            int ra = mbase + qrow, rb = mbase + qrow + 8;
            if (ra < nrows) {
                __half2 h = __floats2half2_rn(silu_(gA[0]) * uA[0], silu_(gA[1]) * uA[1]);
                *(__half2*)&g_h[((size_t)e * CAP + ra) * FFN_ + fbase] = h;
            }
            if (rb < nrows) {
                __half2 h = __floats2half2_rn(silu_(gA[2]) * uA[2], silu_(gA[3]) * uA[3]);
                *(__half2*)&g_h[((size_t)e * CAP + rb) * FFN_ + fbase] = h;
            }
        }
    }
}

// ---------------- K4: down GEMM ----------------------------------------------
__global__ __launch_bounds__(256, 2) void k_down_mma(const float* __restrict__ wd) {
    extern __shared__ __align__(1024) uint8_t sm[];
    const int e = blockIdx.z;
    int nrows = g_cnt[e]; if (nrows > CAP) nrows = CAP;
    const int row0 = blockIdx.y * 128;
    if (row0 >= nrows) return;
    const int d0 = blockIdx.x * 128;

    const int tid = threadIdx.x;
    const int wid = tid >> 5, lane = tid & 31;
    const int wm = wid & 1, wn = wid >> 1;
    const uint32_t sbase = smem_u32(sm);

    const int r0 = tid >> 3, c = tid & 7;
    const uint32_t offa0 = r0 * 128 + ((c * 16) ^ ((r0 & 7) << 4));

    const __half* abase = g_h + ((size_t)e * CAP + row0 + r0) * FFN_ + c * 8;
    const __half* aptr[4];
    #pragma unroll
    for (int i = 0; i < 4; i++) aptr[i] = abase + (size_t)(32 * i) * FFN_;

    const float* bsrc = wd + ((size_t)e * DIM + d0 + r0) * FFN_ + c * 8;
    const int64_t bstride = (int64_t)32 * FFN_;

    float acc[4][4][4];
    mainloop(sm, sbase, aptr, bsrc, bstride, offa0, wm, wn, lane, FFN_ / 64, acc);

    const int qrow = lane >> 2, qcol = (lane & 3) * 2;
    #pragma unroll
    for (int mt = 0; mt < 4; mt++) {
        int mbase = row0 + wm * 64 + mt * 16;
        #pragma unroll
        for (int nt = 0; nt < 4; nt++) {
            int dcol = d0 + wn * 32 + nt * 8 + qcol;
            int ra = mbase + qrow, rb = mbase + qrow + 8;
            if (ra < nrows) {
                __half2 h = __floats2half2_rn(acc[mt][nt][0], acc[mt][nt][1]);
                *(__half2*)&g_y[((size_t)e * CAP + ra) * DIM + dcol] = h;
            }
            if (rb < nrows) {
                __half2 h = __floats2half2_rn(acc[mt][nt][2], acc[mt][nt][3]);
                *(__half2*)&g_y[((size_t)e * CAP + rb) * DIM + dcol] = h;
            }
        }
    }
}

// ---------------- K5: weighted combine (fp16 y, fp32 acc) --------------------
__global__ __launch_bounds__(256) void k_combine(float* __restrict__ out) {
    const int t = blockIdx.x;
    const int tid = threadIdx.x;
    float acc[8];
    #pragma unroll
    for (int i = 0; i < 8; i++) acc[i] = 0.f;
    #pragma unroll
    for (int k = 0; k < TOPK; k++) {
        const int p = t * TOPK + k;
        const int e = g_eid[p];
        const int s = g_slot[p];
        if (s >= CAP) continue;
        const float sc = g_scr[p];
        const uint4* yr = (const uint4*)&g_y[((size_t)e * CAP + s) * DIM];
        uint4 v = yr[tid];
        uint32_t w[4] = {v.x, v.y, v.z, v.w};
        #pragma unroll
        for (int i = 0; i < 4; i++) {
            float2 f = __half22float2(*(__half2*)&w[i]);
            acc[2*i]   += sc * f.x;
            acc[2*i+1] += sc * f.y;
        }
    }
    float* op = out + (size_t)t * DIM + tid * 8;
    *(float4*)op       = make_float4(acc[0], acc[1], acc[2], acc[3]);
    *(float4*)(op + 4) = make_float4(acc[4], acc[5], acc[6], acc[7]);
}

// ---------------- launch -----------------------------------------------------
extern "C" void kernel_launch(void* const* d_in, const int* in_sizes, int n_in,
                              void* d_out, int out_size) {
    (void)in_sizes; (void)n_in; (void)out_size;
    const float* x      = (const float*)d_in[0];
    const float* gate_w = (const float*)d_in[1];
    const float* w_gate = (const float*)d_in[2];
    const float* w_up   = (const float*)d_in[3];
    const float* w_down = (const float*)d_in[4];
    float* out          = (float*)d_out;

    cudaFuncSetAttribute(k_gateup_mma, cudaFuncAttributeMaxDynamicSharedMemorySize, SMEM_DYN);
    cudaFuncSetAttribute(k_down_mma,   cudaFuncAttributeMaxDynamicSharedMemorySize, SMEM_DYN);

    k_gate<<<NT / 4, 256>>>(x, gate_w);
    k_zero<<<1, 64>>>();
    k_route<<<NP / 256, 256>>>();
    k_gateup_mma<<<dim3(FFN_ / 64, CAP / 128, NE), 256, SMEM_DYN>>>(w_gate, w_up);
    k_down_mma<<<dim3(DIM / 128, CAP / 128, NE), 256, SMEM_DYN>>>(w_down);
    k_combine<<<NT, 256>>>(out);
}

// round 12
// speedup vs baseline: 1.3377x; 1.0276x over previous
#include <cuda_runtime.h>
#include <cuda_fp16.h>
#include <cstdint>
#include <math.h>

#define NT   2048
#define DIM  2048
#define FFN_ 768
#define NE   64
#define TOPK 8
#define NP   (NT*TOPK)
#define CAP  512

#define STAGEB 32768                   // A 16KB + B 16KB (128 rows x 64 k fp16)
#define SMEM_DYN (3*STAGEB)            // 3-stage, 96KB/CTA -> 2 CTAs/SM (192KB)

// ---------------- scratch ----------------------------------------------------
__device__ int    g_cnt[NE];
__device__ int    g_tok[NE*CAP];
__device__ int    g_eid[NP];
__device__ int    g_slot[NP];
__device__ float  g_scr[NP];
__device__ __half g_xh[(size_t)NT*DIM];       // 8 MB fp16 tokens
__device__ __half g_h[(size_t)NE*CAP*FFN_];   // 50 MB fp16 activations
__device__ __half g_y[(size_t)NE*CAP*DIM];    // 134 MB fp16 expert outputs

// ---------------- helpers ----------------------------------------------------
__device__ __forceinline__ uint32_t smem_u32(const void* p) {
    uint32_t a;
    asm("{ .reg .u64 t; cvta.to.shared.u64 t, %1; cvt.u32.u64 %0, t; }" : "=r"(a) : "l"(p));
    return a;
}
__device__ __forceinline__ void ldsm4(uint32_t* r, uint32_t addr) {
    asm volatile("ldmatrix.sync.aligned.m8n8.x4.shared.b16 {%0,%1,%2,%3}, [%4];"
                 : "=r"(r[0]), "=r"(r[1]), "=r"(r[2]), "=r"(r[3]) : "r"(addr));
}
__device__ __forceinline__ void mma16816(float* d, const uint32_t* a, const uint32_t* b) {
    asm volatile("mma.sync.aligned.m16n8k16.row.col.f32.f16.f16.f32 "
                 "{%0,%1,%2,%3}, {%4,%5,%6,%7}, {%8,%9}, {%0,%1,%2,%3};"
                 : "+f"(d[0]), "+f"(d[1]), "+f"(d[2]), "+f"(d[3])
                 : "r"(a[0]), "r"(a[1]), "r"(a[2]), "r"(a[3]), "r"(b[0]), "r"(b[1]));
}
__device__ __forceinline__ uint32_t pack2(float a, float b) {
    __half2 h = __floats2half2_rn(a, b);
    return *reinterpret_cast<uint32_t*>(&h);
}
__device__ __forceinline__ uint4 pack8(const float4& u, const float4& v) {
    uint4 p; p.x = pack2(u.x, u.y); p.y = pack2(u.z, u.w);
    p.z = pack2(v.x, v.y); p.w = pack2(v.z, v.w);
    return p;
}
__device__ __forceinline__ float silu_(float g) { return g / (1.f + __expf(-g)); }

#define CP16(s, g) asm volatile("cp.async.cg.shared.global [%0], [%1], 16;" :: "r"(s), "l"(g))
#define CPCOMMIT() asm volatile("cp.async.commit_group;" ::: "memory")
#define CPWAIT1()  asm volatile("cp.async.wait_group 1;" ::: "memory")

// ---------------- K1: gating (fp32 exact) + x->fp16 --------------------------
__global__ __launch_bounds__(256) void k_gate(const float* __restrict__ x,
                                              const float* __restrict__ gw) {
    __shared__ float sx[4][DIM];
    __shared__ float slog[4][NE];
    const int t0 = blockIdx.x * 4;
    const int tid = threadIdx.x;
    for (int i = tid; i < 4 * (DIM / 4); i += 256) {
        int row = i / (DIM / 4), c = i % (DIM / 4);
        ((float4*)sx[row])[c] = ((const float4*)(x + (size_t)(t0 + row) * DIM))[c];
    }
    __syncthreads();
    const int warp = tid >> 5, lane = tid & 31;
    for (int d = warp * 32; d < warp * 32 + 32; d++) {
        int tk = d >> 6, e = d & 63;
        const float* w = gw + (size_t)e * DIM;
        float acc = 0.f;
        for (int i = lane * 4; i < DIM; i += 128) {
            float4 xv = *(const float4*)&sx[tk][i];
            float4 wv = *(const float4*)&w[i];
            acc += xv.x * wv.x + xv.y * wv.y + xv.z * wv.z + xv.w * wv.w;
        }
        #pragma unroll
        for (int o = 16; o; o >>= 1) acc += __shfl_xor_sync(0xffffffffu, acc, o);
        if (lane == 0) slog[tk][e] = acc;
    }
    #pragma unroll
    for (int i = 0; i < 4; i++) {
        int q = tid + 256 * i;
        int row = q >> 8, c = (q & 255) * 8;
        float4 u = *(const float4*)&sx[row][c];
        float4 v = *(const float4*)&sx[row][c + 4];
        *(uint4*)&g_xh[(size_t)(t0 + row) * DIM + c] = pack8(u, v);
    }
    __syncthreads();
    // warp-parallel top-8 per token (warps 0..3)
    if (warp < 4) {
        const int tk = warp, token = t0 + tk;
        float l0 = slog[tk][lane], l1 = slog[tk][lane + 32];
        float m = fmaxf(l0, l1);
        #pragma unroll
        for (int o = 16; o; o >>= 1) m = fmaxf(m, __shfl_xor_sync(0xffffffffu, m, o));
        float p0 = __expf(l0 - m), p1 = __expf(l1 - m);
        float s = p0 + p1;
        #pragma unroll
        for (int o = 16; o; o >>= 1) s += __shfl_xor_sync(0xffffffffu, s, o);
        const float inv = 1.f / s;
        #pragma unroll
        for (int k = 0; k < TOPK; k++) {
            float v; int ei;
            if (p0 >= p1) { v = p0; ei = lane; } else { v = p1; ei = lane + 32; }
            #pragma unroll
            for (int o = 16; o; o >>= 1) {
                float ov = __shfl_xor_sync(0xffffffffu, v, o);
                int   oe = __shfl_xor_sync(0xffffffffu, ei, o);
                if (ov > v || (ov == v && oe < ei)) { v = ov; ei = oe; }
            }
            if (lane == 0) {
                g_eid[token * TOPK + k] = ei;
                g_scr[token * TOPK + k] = v * inv;
            }
            if (ei < 32)  { if (lane == ei)      p0 = -2.f; }
            else          { if (lane == ei - 32) p1 = -2.f; }
        }
    }
}

// ---------------- K2: routing ------------------------------------------------
__global__ void k_zero() { if (threadIdx.x < NE) g_cnt[threadIdx.x] = 0; }
__global__ void k_route() {
    int p = blockIdx.x * 256 + threadIdx.x;
    if (p >= NP) return;
    int e = g_eid[p];
    int slot = atomicAdd(&g_cnt[e], 1);
    g_slot[p] = slot;
    if (slot < CAP) g_tok[e * CAP + slot] = p >> 3;
}

// == 128x128 fp16 MMA mainloop: 256 thr, 8 warps (2m x 4n), 64x32 warp tile ==
// 3-stage cp.async pipeline (wait_group 1). A via cp.async; B LDG->pack->STS.
__device__ __forceinline__ void mainloop(
    uint8_t* sm, uint32_t sbase,
    const __half* const (&aptr)[4],
    const float* bsrc, int64_t bstride,
    uint32_t offa0,
    int wm, int wn, int lane, int NK, float (&acc)[4][4][4])
{
    #pragma unroll
    for (int a = 0; a < 4; a++)
        #pragma unroll
        for (int b = 0; b < 4; b++)
            #pragma unroll
            for (int c = 0; c < 4; c++) acc[a][b][c] = 0.f;

    // prologue: A(0),A(1) cp.async (2 groups); B(0) STS; B(1) -> regs
    #pragma unroll
    for (int s = 0; s < 2; s++) {
        #pragma unroll
        for (int i = 0; i < 4; i++)
            CP16(sbase + s * STAGEB + offa0 + i * 4096, aptr[i] + s * 64);
        CPCOMMIT();
    }
    #pragma unroll
    for (int i = 0; i < 4; i++) {
        float4 u = *(const float4*)(bsrc + i * bstride);
        float4 v = *(const float4*)(bsrc + i * bstride + 4);
        *(uint4*)(sm + 16384 + offa0 + i * 4096) = pack8(u, v);
    }
    uint4 vb[4];
    #pragma unroll
    for (int i = 0; i < 4; i++) {
        float4 u = *(const float4*)(bsrc + i * bstride + 64);
        float4 v = *(const float4*)(bsrc + i * bstride + 68);
        vb[i] = pack8(u, v);
    }

    uint32_t cur = 0, nxt = STAGEB, nx2 = 2 * STAGEB;
    #pragma unroll 1
    for (int j = 0; j < NK; j++) {
        CPWAIT1();
        __syncthreads();
        // A(j+2) cp.async into stage nx2
        if (j + 2 < NK) {
            #pragma unroll
            for (int i = 0; i < 4; i++)
                CP16(sbase + nx2 + offa0 + i * 4096, aptr[i] + (j + 2) * 64);
        }
        CPCOMMIT();                    // one group per iteration
        // STS B(j+1) (pre-packed)
        if (j + 1 < NK) {
            #pragma unroll
            for (int i = 0; i < 4; i++)
                *(uint4*)(sm + nxt + 16384 + offa0 + i * 4096) = vb[i];
        }
        // LDG+pack B(j+2)
        if (j + 2 < NK) {
            #pragma unroll
            for (int i = 0; i < 4; i++) {
                float4 u = *(const float4*)(bsrc + i * bstride + (j + 2) * 64);
                float4 v = *(const float4*)(bsrc + i * bstride + (j + 2) * 64 + 4);
                vb[i] = pack8(u, v);
            }
        }
        // MMA(j)
        const uint32_t sA = sbase + cur, sB = sA + 16384;
        #pragma unroll
        for (int ks = 0; ks < 4; ks++) {
            uint32_t af[4][4], bf[2][4];
            #pragma unroll
            for (int n2 = 0; n2 < 2; n2++) {
                int row = wn * 32 + n2 * 16 + ((lane >> 4) << 3) + (lane & 7);
                int byt = ks * 32 + (((lane >> 3) & 1) << 4);
                ldsm4(bf[n2], sB + row * 128 + (byt ^ ((row & 7) << 4)));
            }
            #pragma unroll
            for (int mt = 0; mt < 4; mt++) {
                int row = wm * 64 + mt * 16 + (lane & 15);
                int byt = ks * 32 + ((lane >> 4) << 4);
                ldsm4(af[mt], sA + row * 128 + (byt ^ ((row & 7) << 4)));
            }
            #pragma unroll
            for (int mt = 0; mt < 4; mt++)
                #pragma unroll
                for (int nt = 0; nt < 4; nt++)
                    mma16816(acc[mt][nt], af[mt], &bf[nt >> 1][(nt & 1) * 2]);
        }
        uint32_t t = cur; cur = nxt; nxt = nx2; nx2 = t;
    }
}

// ---------------- K3: gate/up GEMM + SwiGLU ----------------------------------
__global__ __launch_bounds__(256, 2) void k_gateup_mma(const float* __restrict__ wg,
                                                       const float* __restrict__ wu) {
    extern __shared__ __align__(1024) uint8_t sm[];
    const int e = blockIdx.z;
    int nrows = g_cnt[e]; if (nrows > CAP) nrows = CAP;
    const int row0 = blockIdx.y * 128;
    if (row0 >= nrows) return;
    const int f0 = blockIdx.x * 64;

    const int tid = threadIdx.x;
    const int wid = tid >> 5, lane = tid & 31;
    const int wm = wid & 1, wn = wid >> 1;
    const uint32_t sbase = smem_u32(sm);

    const int r0 = tid >> 3, c = tid & 7;
    const uint32_t offa0 = r0 * 128 + ((c * 16) ^ ((r0 & 7) << 4));

    const __half* aptr[4];
    #pragma unroll
    for (int i = 0; i < 4; i++) {
        int rr = row0 + r0 + 32 * i;
        int tok = g_tok[e * CAP + (rr < nrows ? rr : 0)];
        aptr[i] = g_xh + (size_t)tok * DIM + c * 8;
    }
    const int t8 = r0 >> 3, w8 = r0 & 7;
    const int fr = f0 + (t8 >> 1) * 8 + w8;
    const float* wb = (t8 & 1) ? wu : wg;
    const float* bsrc = wb + ((size_t)e * FFN_ + fr) * DIM + c * 8;
    const int64_t bstride = (int64_t)16 * DIM;

    float acc[4][4][4];
    mainloop(sm, sbase, aptr, bsrc, bstride, offa0, wm, wn, lane, DIM / 64, acc);

    const int qrow = lane >> 2, qcol = (lane & 3) * 2;
    #pragma unroll
    for (int mt = 0; mt < 4; mt++) {
        int mbase = row0 + wm * 64 + mt * 16;
        #pragma unroll
        for (int p = 0; p < 2; p++) {
            int fbase = f0 + (wn * 2 + p) * 8 + qcol;
            float* gA = acc[mt][2 * p];
            float* uA = acc[mt][2 * p + 1];
            int ra = mbase + qrow, rb = mbase + qrow + 8;
            if (ra < nrows) {
                __half2 h = __floats2half2_rn(silu_(gA[0]) * uA[0], silu_(gA[1]) * uA[1]);
                *(__half2*)&g_h[((size_t)e * CAP + ra) * FFN_ + fbase] = h;
            }
            if (rb < nrows) {
                __half2 h = __floats2half2_rn(silu_(gA[2]) * uA[2], silu_(gA[3]) * uA[3]);
                *(__half2*)&g_h[((size_t)e * CAP + rb) * FFN_ + fbase] = h;
            }
        }
    }
}

// ---------------- K4: down GEMM ----------------------------------------------
__global__ __launch_bounds__(256, 2) void k_down_mma(const float* __restrict__ wd) {
    extern __shared__ __align__(1024) uint8_t sm[];
    const int e = blockIdx.z;
    int nrows = g_cnt[e]; if (nrows > CAP) nrows = CAP;
    const int row0 = blockIdx.y * 128;
    if (row0 >= nrows) return;
    const int d0 = blockIdx.x * 128;

    const int tid = threadIdx.x;
    const int wid = tid >> 5, lane = tid & 31;
    const int wm = wid & 1, wn = wid >> 1;
    const uint32_t sbase = smem_u32(sm);

    const int r0 = tid >> 3, c = tid & 7;
    const uint32_t offa0 = r0 * 128 + ((c * 16) ^ ((r0 & 7) << 4));

    const __half* abase = g_h + ((size_t)e * CAP + row0 + r0) * FFN_ + c * 8;
    const __half* aptr[4];
    #pragma unroll
    for (int i = 0; i < 4; i++) aptr[i] = abase + (size_t)(32 * i) * FFN_;

    const float* bsrc = wd + ((size_t)e * DIM + d0 + r0) * FFN_ + c * 8;
    const int64_t bstride = (int64_t)32 * FFN_;

    float acc[4][4][4];
    mainloop(sm, sbase, aptr, bsrc, bstride, offa0, wm, wn, lane, FFN_ / 64, acc);

    const int qrow = lane >> 2, qcol = (lane & 3) * 2;
    #pragma unroll
    for (int mt = 0; mt < 4; mt++) {
        int mbase = row0 + wm * 64 + mt * 16;
        #pragma unroll
        for (int nt = 0; nt < 4; nt++) {
            int dcol = d0 + wn * 32 + nt * 8 + qcol;
            int ra = mbase + qrow, rb = mbase + qrow + 8;
            if (ra < nrows) {
                __half2 h = __floats2half2_rn(acc[mt][nt][0], acc[mt][nt][1]);
                *(__half2*)&g_y[((size_t)e * CAP + ra) * DIM + dcol] = h;
            }
            if (rb < nrows) {
                __half2 h = __floats2half2_rn(acc[mt][nt][2], acc[mt][nt][3]);
                *(__half2*)&g_y[((size_t)e * CAP + rb) * DIM + dcol] = h;
            }
        }
    }
}

// ---------------- K5: weighted combine (fp16 y, fp32 acc) --------------------
__global__ __launch_bounds__(256) void k_combine(float* __restrict__ out) {
    const int t = blockIdx.x;
    const int tid = threadIdx.x;
    float acc[8];
    #pragma unroll
    for (int i = 0; i < 8; i++) acc[i] = 0.f;
    #pragma unroll
    for (int k = 0; k < TOPK; k++) {
        const int p = t * TOPK + k;
        const int e = g_eid[p];
        const int s = g_slot[p];
        if (s >= CAP) continue;
        const float sc = g_scr[p];
        const uint4* yr = (const uint4*)&g_y[((size_t)e * CAP + s) * DIM];
        uint4 v = yr[tid];
        uint32_t w[4] = {v.x, v.y, v.z, v.w};
        #pragma unroll
        for (int i = 0; i < 4; i++) {
            float2 f = __half22float2(*(__half2*)&w[i]);
            acc[2*i]   += sc * f.x;
            acc[2*i+1] += sc * f.y;
        }
    }
    float* op = out + (size_t)t * DIM + tid * 8;
    *(float4*)op       = make_float4(acc[0], acc[1], acc[2], acc[3]);
    *(float4*)(op + 4) = make_float4(acc[4], acc[5], acc[6], acc[7]);
}

// ---------------- launch -----------------------------------------------------
extern "C" void kernel_launch(void* const* d_in, const int* in_sizes, int n_in,
                              void* d_out, int out_size) {
    (void)in_sizes; (void)n_in; (void)out_size;
    const float* x      = (const float*)d_in[0];
    const float* gate_w = (const float*)d_in[1];
    const float* w_gate = (const float*)d_in[2];
    const float* w_up   = (const float*)d_in[3];
    const float* w_down = (const float*)d_in[4];
    float* out          = (float*)d_out;

    cudaFuncSetAttribute(k_gateup_mma, cudaFuncAttributeMaxDynamicSharedMemorySize, SMEM_DYN);
    cudaFuncSetAttribute(k_down_mma,   cudaFuncAttributeMaxDynamicSharedMemorySize, SMEM_DYN);

    k_gate<<<NT / 4, 256>>>(x, gate_w);
    k_zero<<<1, 64>>>();
    k_route<<<NP / 256, 256>>>();
    k_gateup_mma<<<dim3(FFN_ / 64, CAP / 128, NE), 256, SMEM_DYN>>>(w_gate, w_up);
    k_down_mma<<<dim3(DIM / 128, CAP / 128, NE), 256, SMEM_DYN>>>(w_down);
    k_combine<<<NT, 256>>>(out);
}

// round 14
// speedup vs baseline: 1.3529x; 1.0113x over previous
#include <cuda_runtime.h>
#include <cuda_fp16.h>
#include <cstdint>
#include <math.h>

#define NT   2048
#define DIM  2048
#define FFN_ 768
#define NE   64
#define TOPK 8
#define NP   (NT*TOPK)
#define CAP  512

#define STAGEB 32768                   // A 16KB + B 16KB (128 rows x 64 k fp16)
#define SMEM_DYN (3*STAGEB)            // 3-stage, 96KB/CTA -> 2 CTAs/SM (192KB)

// ---------------- scratch ----------------------------------------------------
__device__ int    g_cnt[NE];
__device__ int    g_tok[NE*CAP];
__device__ int    g_eid[NP];
__device__ int    g_slot[NP];
__device__ float  g_scr[NP];
__device__ __half g_xh[(size_t)NT*DIM];       // 8 MB fp16 tokens
__device__ __half g_h[(size_t)NE*CAP*FFN_];   // 50 MB fp16 activations
__device__ __half g_y[(size_t)NE*CAP*DIM];    // 134 MB fp16 expert outputs

// ---------------- helpers ----------------------------------------------------
__device__ __forceinline__ uint32_t smem_u32(const void* p) {
    uint32_t a;
    asm("{ .reg .u64 t; cvta.to.shared.u64 t, %1; cvt.u32.u64 %0, t; }" : "=r"(a) : "l"(p));
    return a;
}
__device__ __forceinline__ void ldsm4(uint32_t* r, uint32_t addr) {
    asm volatile("ldmatrix.sync.aligned.m8n8.x4.shared.b16 {%0,%1,%2,%3}, [%4];"
                 : "=r"(r[0]), "=r"(r[1]), "=r"(r[2]), "=r"(r[3]) : "r"(addr));
}
__device__ __forceinline__ void mma16816(float* d, const uint32_t* a, const uint32_t* b) {
    asm volatile("mma.sync.aligned.m16n8k16.row.col.f32.f16.f16.f32 "
                 "{%0,%1,%2,%3}, {%4,%5,%6,%7}, {%8,%9}, {%0,%1,%2,%3};"
                 : "+f"(d[0]), "+f"(d[1]), "+f"(d[2]), "+f"(d[3])
                 : "r"(a[0]), "r"(a[1]), "r"(a[2]), "r"(a[3]), "r"(b[0]), "r"(b[1]));
}
__device__ __forceinline__ uint32_t pack2(float a, float b) {
    __half2 h = __floats2half2_rn(a, b);
    return *reinterpret_cast<uint32_t*>(&h);
}
__device__ __forceinline__ uint4 pack8(const float4& u, const float4& v) {
    uint4 p; p.x = pack2(u.x, u.y); p.y = pack2(u.z, u.w);
    p.z = pack2(v.x, v.y); p.w = pack2(v.z, v.w);
    return p;
}
__device__ __forceinline__ float silu_(float g) {
    return __fdividef(g, 1.f + __expf(-g));
}

#define CP16(s, g) asm volatile("cp.async.cg.shared.global [%0], [%1], 16;" :: "r"(s), "l"(g))
#define CPCOMMIT() asm volatile("cp.async.commit_group;" ::: "memory")
#define CPWAIT1()  asm volatile("cp.async.wait_group 1;" ::: "memory")

// ---------------- K0: zero expert counters -----------------------------------
__global__ void k_zero() { if (threadIdx.x < NE) g_cnt[threadIdx.x] = 0; }

// ------- K1: gating (fp32 exact) + x->fp16 + fused routing -------------------
__global__ __launch_bounds__(256) void k_gate(const float* __restrict__ x,
                                              const float* __restrict__ gw) {
    __shared__ float sx[4][DIM];
    __shared__ float slog[4][NE];
    const int t0 = blockIdx.x * 4;
    const int tid = threadIdx.x;
    for (int i = tid; i < 4 * (DIM / 4); i += 256) {
        int row = i / (DIM / 4), c = i % (DIM / 4);
        ((float4*)sx[row])[c] = ((const float4*)(x + (size_t)(t0 + row) * DIM))[c];
    }
    __syncthreads();
    const int warp = tid >> 5, lane = tid & 31;
    for (int d = warp * 32; d < warp * 32 + 32; d++) {
        int tk = d >> 6, e = d & 63;
        const float* w = gw + (size_t)e * DIM;
        float acc = 0.f;
        for (int i = lane * 4; i < DIM; i += 128) {
            float4 xv = *(const float4*)&sx[tk][i];
            float4 wv = *(const float4*)&w[i];
            acc += xv.x * wv.x + xv.y * wv.y + xv.z * wv.z + xv.w * wv.w;
        }
        #pragma unroll
        for (int o = 16; o; o >>= 1) acc += __shfl_xor_sync(0xffffffffu, acc, o);
        if (lane == 0) slog[tk][e] = acc;
    }
    #pragma unroll
    for (int i = 0; i < 4; i++) {
        int q = tid + 256 * i;
        int row = q >> 8, c = (q & 255) * 8;
        float4 u = *(const float4*)&sx[row][c];
        float4 v = *(const float4*)&sx[row][c + 4];
        *(uint4*)&g_xh[(size_t)(t0 + row) * DIM + c] = pack8(u, v);
    }
    __syncthreads();
    // warp-parallel top-8 per token (warps 0..3) + fused slot routing
    if (warp < 4) {
        const int tk = warp, token = t0 + tk;
        float l0 = slog[tk][lane], l1 = slog[tk][lane + 32];
        float m = fmaxf(l0, l1);
        #pragma unroll
        for (int o = 16; o; o >>= 1) m = fmaxf(m, __shfl_xor_sync(0xffffffffu, m, o));
        float p0 = __expf(l0 - m), p1 = __expf(l1 - m);
        float s = p0 + p1;
        #pragma unroll
        for (int o = 16; o; o >>= 1) s += __shfl_xor_sync(0xffffffffu, s, o);
        const float inv = 1.f / s;
        int   my_e = 0;
        float my_s = 0.f;
        #pragma unroll
        for (int k = 0; k < TOPK; k++) {
            float v; int ei;
            if (p0 >= p1) { v = p0; ei = lane; } else { v = p1; ei = lane + 32; }
            #pragma unroll
            for (int o = 16; o; o >>= 1) {
                float ov = __shfl_xor_sync(0xffffffffu, v, o);
                int   oe = __shfl_xor_sync(0xffffffffu, ei, o);
                if (ov > v || (ov == v && oe < ei)) { v = ov; ei = oe; }
            }
            if (lane == k) { my_e = ei; my_s = v * inv; }
            if (ei < 32)  { if (lane == ei)      p0 = -2.f; }
            else          { if (lane == ei - 32) p1 = -2.f; }
        }
        if (lane < TOPK) {
            const int p = token * TOPK + lane;
            g_eid[p] = my_e;
            g_scr[p] = my_s;
            int slot = atomicAdd(&g_cnt[my_e], 1);
            g_slot[p] = slot;
            if (slot < CAP) g_tok[my_e * CAP + slot] = token;
        }
    }
}

// == 128x128 fp16 MMA mainloop: 256 thr, 8 warps (2m x 4n), 64x32 warp tile ==
// 3-stage cp.async pipeline (wait_group 1). A via cp.async; B LDG->pack->STS.
__device__ __forceinline__ void mainloop(
    uint8_t* sm, uint32_t sbase,
    const __half* const (&aptr)[4],
    const float* bsrc, int64_t bstride,
    uint32_t offa0,
    int wm, int wn, int lane, int NK, float (&acc)[4][4][4])
{
    #pragma unroll
    for (int a = 0; a < 4; a++)
        #pragma unroll
        for (int b = 0; b < 4; b++)
            #pragma unroll
            for (int c = 0; c < 4; c++) acc[a][b][c] = 0.f;

    // prologue: A(0),A(1) cp.async (2 groups); B(0) STS; B(1) -> regs
    #pragma unroll
    for (int s = 0; s < 2; s++) {
        #pragma unroll
        for (int i = 0; i < 4; i++)
            CP16(sbase + s * STAGEB + offa0 + i * 4096, aptr[i] + s * 64);
        CPCOMMIT();
    }
    #pragma unroll
    for (int i = 0; i < 4; i++) {
        float4 u = *(const float4*)(bsrc + i * bstride);
        float4 v = *(const float4*)(bsrc + i * bstride + 4);
        *(uint4*)(sm + 16384 + offa0 + i * 4096) = pack8(u, v);
    }
    uint4 vb[4];
    #pragma unroll
    for (int i = 0; i < 4; i++) {
        float4 u = *(const float4*)(bsrc + i * bstride + 64);
        float4 v = *(const float4*)(bsrc + i * bstride + 68);
        vb[i] = pack8(u, v);
    }

    uint32_t cur = 0, nxt = STAGEB, nx2 = 2 * STAGEB;
    #pragma unroll 1
    for (int j = 0; j < NK; j++) {
        CPWAIT1();
        __syncthreads();
        // A(j+2) cp.async into stage nx2
        if (j + 2 < NK) {
            #pragma unroll
            for (int i = 0; i < 4; i++)
                CP16(sbase + nx2 + offa0 + i * 4096, aptr[i] + (j + 2) * 64);
        }
        CPCOMMIT();                    // one group per iteration
        // STS B(j+1) (pre-packed)
        if (j + 1 < NK) {
            #pragma unroll
            for (int i = 0; i < 4; i++)
                *(uint4*)(sm + nxt + 16384 + offa0 + i * 4096) = vb[i];
        }
        // LDG+pack B(j+2)
        if (j + 2 < NK) {
            #pragma unroll
            for (int i = 0; i < 4; i++) {
                float4 u = *(const float4*)(bsrc + i * bstride + (j + 2) * 64);
                float4 v = *(const float4*)(bsrc + i * bstride + (j + 2) * 64 + 4);
                vb[i] = pack8(u, v);
            }
        }
        // MMA(j)
        const uint32_t sA = sbase + cur, sB = sA + 16384;
        #pragma unroll
        for (int ks = 0; ks < 4; ks++) {
            uint32_t af[4][4], bf[2][4];
            #pragma unroll
            for (int n2 = 0; n2 < 2; n2++) {
                int row = wn * 32 + n2 * 16 + ((lane >> 4) << 3) + (lane & 7);
                int byt = ks * 32 + (((lane >> 3) & 1) << 4);
                ldsm4(bf[n2], sB + row * 128 + (byt ^ ((row & 7) << 4)));
            }
            #pragma unroll
            for (int mt = 0; mt < 4; mt++) {
                int row = wm * 64 + mt * 16 + (lane & 15);
                int byt = ks * 32 + ((lane >> 4) << 4);
                ldsm4(af[mt], sA + row * 128 + (byt ^ ((row & 7) << 4)));
            }
            #pragma unroll
            for (int mt = 0; mt < 4; mt++)
                #pragma unroll
                for (int nt = 0; nt < 4; nt++)
                    mma16816(acc[mt][nt], af[mt], &bf[nt >> 1][(nt & 1) * 2]);
        }
        uint32_t t = cur; cur = nxt; nxt = nx2; nx2 = t;
    }
}

// ---------------- K3: gate/up GEMM + SwiGLU ----------------------------------
__global__ __launch_bounds__(256, 2) void k_gateup_mma(const float* __restrict__ wg,
                                                       const float* __restrict__ wu) {
    extern __shared__ __align__(1024) uint8_t sm[];
    const int e = blockIdx.z;
    int nrows = g_cnt[e]; if (nrows > CAP) nrows = CAP;
    const int row0 = blockIdx.y * 128;
    if (row0 >= nrows) return;
    const int f0 = blockIdx.x * 64;

    const int tid = threadIdx.x;
    const int wid = tid >> 5, lane = tid & 31;
    const int wm = wid & 1, wn = wid >> 1;
    const uint32_t sbase = smem_u32(sm);

    const int r0 = tid >> 3, c = tid & 7;
    const uint32_t offa0 = r0 * 128 + ((c * 16) ^ ((r0 & 7) << 4));

    const __half* aptr[4];
    #pragma unroll
    for (int i = 0; i < 4; i++) {
        int rr = row0 + r0 + 32 * i;
        int tok = g_tok[e * CAP + (rr < nrows ? rr : 0)];
        aptr[i] = g_xh + (size_t)tok * DIM + c * 8;
    }
    const int t8 = r0 >> 3, w8 = r0 & 7;
    const int fr = f0 + (t8 >> 1) * 8 + w8;
    const float* wb = (t8 & 1) ? wu : wg;
    const float* bsrc = wb + ((size_t)e * FFN_ + fr) * DIM + c * 8;
    const int64_t bstride = (int64_t)16 * DIM;

    float acc[4][4][4];
    mainloop(sm, sbase, aptr, bsrc, bstride, offa0, wm, wn, lane, DIM / 64, acc);

    const int qrow = lane >> 2, qcol = (lane & 3) * 2;
    #pragma unroll
    for (int mt = 0; mt < 4; mt++) {
        int mbase = row0 + wm * 64 + mt * 16;
        #pragma unroll
        for (int p = 0; p < 2; p++) {
            int fbase = f0 + (wn * 2 + p) * 8 + qcol;
            float* gA = acc[mt][2 * p];
            float* uA = acc[mt][2 * p + 1];
            int ra = mbase + qrow, rb = mbase + qrow + 8;
            if (ra < nrows) {
                __half2 h = __floats2half2_rn(silu_(gA[0]) * uA[0], silu_(gA[1]) * uA[1]);
                *(__half2*)&g_h[((size_t)e * CAP + ra) * FFN_ + fbase] = h;
            }
            if (rb < nrows) {
                __half2 h = __floats2half2_rn(silu_(gA[2]) * uA[2], silu_(gA[3]) * uA[3]);
                *(__half2*)&g_h[((size_t)e * CAP + rb) * FFN_ + fbase] = h;
            }
        }
    }
}

// ---------------- K4: down GEMM ----------------------------------------------
__global__ __launch_bounds__(256, 2) void k_down_mma(const float* __restrict__ wd) {
    extern __shared__ __align__(1024) uint8_t sm[];
    const int e = blockIdx.z;
    int nrows = g_cnt[e]; if (nrows > CAP) nrows = CAP;
    const int row0 = blockIdx.y * 128;
    if (row0 >= nrows) return;
    const int d0 = blockIdx.x * 128;

    const int tid = threadIdx.x;
    const int wid = tid >> 5, lane = tid & 31;
    const int wm = wid & 1, wn = wid >> 1;
    const uint32_t sbase = smem_u32(sm);

    const int r0 = tid >> 3, c = tid & 7;
    const uint32_t offa0 = r0 * 128 + ((c * 16) ^ ((r0 & 7) << 4));

    const __half* abase = g_h + ((size_t)e * CAP + row0 + r0) * FFN_ + c * 8;
    const __half* aptr[4];
    #pragma unroll
    for (int i = 0; i < 4; i++) aptr[i] = abase + (size_t)(32 * i) * FFN_;

    const float* bsrc = wd + ((size_t)e * DIM + d0 + r0) * FFN_ + c * 8;
    const int64_t bstride = (int64_t)32 * FFN_;

    float acc[4][4][4];
    mainloop(sm, sbase, aptr, bsrc, bstride, offa0, wm, wn, lane, FFN_ / 64, acc);

    const int qrow = lane >> 2, qcol = (lane & 3) * 2;
    #pragma unroll
    for (int mt = 0; mt < 4; mt++) {
        int mbase = row0 + wm * 64 + mt * 16;
        #pragma unroll
        for (int nt = 0; nt < 4; nt++) {
            int dcol = d0 + wn * 32 + nt * 8 + qcol;
            int ra = mbase + qrow, rb = mbase + qrow + 8;
            if (ra < nrows) {
                __half2 h = __floats2half2_rn(acc[mt][nt][0], acc[mt][nt][1]);
                *(__half2*)&g_y[((size_t)e * CAP + ra) * DIM + dcol] = h;
            }
            if (rb < nrows) {
                __half2 h = __floats2half2_rn(acc[mt][nt][2], acc[mt][nt][3]);
                *(__half2*)&g_y[((size_t)e * CAP + rb) * DIM + dcol] = h;
            }
        }
    }
}

// ---------------- K5: weighted combine (fp16 y, fp32 acc) --------------------
__global__ __launch_bounds__(256) void k_combine(float* __restrict__ out) {
    const int t = blockIdx.x;
    const int tid = threadIdx.x;
    float acc[8];
    #pragma unroll
    for (int i = 0; i < 8; i++) acc[i] = 0.f;
    #pragma unroll
    for (int k = 0; k < TOPK; k++) {
        const int p = t * TOPK + k;
        const int e = g_eid[p];
        const int s = g_slot[p];
        if (s >= CAP) continue;
        const float sc = g_scr[p];
        const uint4* yr = (const uint4*)&g_y[((size_t)e * CAP + s) * DIM];
        uint4 v = yr[tid];
        uint32_t w[4] = {v.x, v.y, v.z, v.w};
        #pragma unroll
        for (int i = 0; i < 4; i++) {
            float2 f = __half22float2(*(__half2*)&w[i]);
            acc[2*i]   += sc * f.x;
            acc[2*i+1] += sc * f.y;
        }
    }
    float* op = out + (size_t)t * DIM + tid * 8;
    *(float4*)op       = make_float4(acc[0], acc[1], acc[2], acc[3]);
    *(float4*)(op + 4) = make_float4(acc[4], acc[5], acc[6], acc[7]);
}

// ---------------- launch -----------------------------------------------------
extern "C" void kernel_launch(void* const* d_in, const int* in_sizes, int n_in,
                              void* d_out, int out_size) {
    (void)in_sizes; (void)n_in; (void)out_size;
    const float* x      = (const float*)d_in[0];
    const float* gate_w = (const float*)d_in[1];
    const float* w_gate = (const float*)d_in[2];
    const float* w_up   = (const float*)d_in[3];
    const float* w_down = (const float*)d_in[4];
    float* out          = (float*)d_out;

    cudaFuncSetAttribute(k_gateup_mma, cudaFuncAttributeMaxDynamicSharedMemorySize, SMEM_DYN);
    cudaFuncSetAttribute(k_down_mma,   cudaFuncAttributeMaxDynamicSharedMemorySize, SMEM_DYN);

    k_zero<<<1, 64>>>();
    k_gate<<<NT / 4, 256>>>(x, gate_w);
    k_gateup_mma<<<dim3(FFN_ / 64, CAP / 128, NE), 256, SMEM_DYN>>>(w_gate, w_up);
    k_down_mma<<<dim3(DIM / 128, CAP / 128, NE), 256, SMEM_DYN>>>(w_down);
    k_combine<<<NT, 256>>>(out);
}

// round 16
// speedup vs baseline: 1.3869x; 1.0252x over previous
#include <cuda_runtime.h>
#include <cuda_fp16.h>
#include <cstdint>
#include <math.h>

#define NT   2048
#define DIM  2048
#define FFN_ 768
#define NE   64
#define TOPK 8
#define NP   (NT*TOPK)
#define CAP  512

#define STAGEB 32768                   // A 16KB + B 16KB (128 rows x 64 k fp16)
#define SMEM_DYN (3*STAGEB)            // 3-stage, 96KB/CTA -> 2 CTAs/SM (192KB)

// ---------------- scratch ----------------------------------------------------
__device__ int    g_cnt[NE];
__device__ int    g_tok[NE*CAP];
__device__ int    g_eid[NP];
__device__ int    g_slot[NP];
__device__ float  g_scr[NP];
__device__ __half g_xh[(size_t)NT*DIM];       // 8 MB fp16 tokens
__device__ __half g_h[(size_t)NE*CAP*FFN_];   // 50 MB fp16 activations
__device__ __half g_y[(size_t)NE*CAP*DIM];    // 134 MB fp16 expert outputs

// ---------------- helpers ----------------------------------------------------
__device__ __forceinline__ uint32_t smem_u32(const void* p) {
    uint32_t a;
    asm("{ .reg .u64 t; cvta.to.shared.u64 t, %1; cvt.u32.u64 %0, t; }" : "=r"(a) : "l"(p));
    return a;
}
__device__ __forceinline__ void ldsm4(uint32_t* r, uint32_t addr) {
    asm volatile("ldmatrix.sync.aligned.m8n8.x4.shared.b16 {%0,%1,%2,%3}, [%4];"
                 : "=r"(r[0]), "=r"(r[1]), "=r"(r[2]), "=r"(r[3]) : "r"(addr));
}
__device__ __forceinline__ void mma16816(float* d, const uint32_t* a, const uint32_t* b) {
    asm volatile("mma.sync.aligned.m16n8k16.row.col.f32.f16.f16.f32 "
                 "{%0,%1,%2,%3}, {%4,%5,%6,%7}, {%8,%9}, {%0,%1,%2,%3};"
                 : "+f"(d[0]), "+f"(d[1]), "+f"(d[2]), "+f"(d[3])
                 : "r"(a[0]), "r"(a[1]), "r"(a[2]), "r"(a[3]), "r"(b[0]), "r"(b[1]));
}
__device__ __forceinline__ uint32_t pack2(float a, float b) {
    __half2 h = __floats2half2_rn(a, b);
    return *reinterpret_cast<uint32_t*>(&h);
}
__device__ __forceinline__ uint4 pack8(const float4& u, const float4& v) {
    uint4 p; p.x = pack2(u.x, u.y); p.y = pack2(u.z, u.w);
    p.z = pack2(v.x, v.y); p.w = pack2(v.z, v.w);
    return p;
}
__device__ __forceinline__ float silu_(float g) {
    return __fdividef(g, 1.f + __expf(-g));
}

#define CP16(s, g) asm volatile("cp.async.cg.shared.global [%0], [%1], 16;" :: "r"(s), "l"(g))
#define CPCOMMIT() asm volatile("cp.async.commit_group;" ::: "memory")
#define CPWAIT1()  asm volatile("cp.async.wait_group 1;" ::: "memory")

// ---------------- K0: zero expert counters -----------------------------------
__global__ void k_zero() { if (threadIdx.x < NE) g_cnt[threadIdx.x] = 0; }

// ------- K1: gating (fp32 exact) + x->fp16 + fused routing -------------------
__global__ __launch_bounds__(256) void k_gate(const float* __restrict__ x,
                                              const float* __restrict__ gw) {
    __shared__ float sx[4][DIM];
    __shared__ float slog[4][NE];
    const int t0 = blockIdx.x * 4;
    const int tid = threadIdx.x;
    for (int i = tid; i < 4 * (DIM / 4); i += 256) {
        int row = i / (DIM / 4), c = i % (DIM / 4);
        ((float4*)sx[row])[c] = ((const float4*)(x + (size_t)(t0 + row) * DIM))[c];
    }
    __syncthreads();
    const int warp = tid >> 5, lane = tid & 31;
    for (int d = warp * 32; d < warp * 32 + 32; d++) {
        int tk = d >> 6, e = d & 63;
        const float* w = gw + (size_t)e * DIM;
        float acc = 0.f;
        for (int i = lane * 4; i < DIM; i += 128) {
            float4 xv = *(const float4*)&sx[tk][i];
            float4 wv = *(const float4*)&w[i];
            acc += xv.x * wv.x + xv.y * wv.y + xv.z * wv.z + xv.w * wv.w;
        }
        #pragma unroll
        for (int o = 16; o; o >>= 1) acc += __shfl_xor_sync(0xffffffffu, acc, o);
        if (lane == 0) slog[tk][e] = acc;
    }
    #pragma unroll
    for (int i = 0; i < 4; i++) {
        int q = tid + 256 * i;
        int row = q >> 8, c = (q & 255) * 8;
        float4 u = *(const float4*)&sx[row][c];
        float4 v = *(const float4*)&sx[row][c + 4];
        *(uint4*)&g_xh[(size_t)(t0 + row) * DIM + c] = pack8(u, v);
    }
    __syncthreads();
    // warp-parallel top-8 per token (warps 0..3) + fused slot routing
    if (warp < 4) {
        const int tk = warp, token = t0 + tk;
        float l0 = slog[tk][lane], l1 = slog[tk][lane + 32];
        float m = fmaxf(l0, l1);
        #pragma unroll
        for (int o = 16; o; o >>= 1) m = fmaxf(m, __shfl_xor_sync(0xffffffffu, m, o));
        float p0 = __expf(l0 - m), p1 = __expf(l1 - m);
        float s = p0 + p1;
        #pragma unroll
        for (int o = 16; o; o >>= 1) s += __shfl_xor_sync(0xffffffffu, s, o);
        const float inv = 1.f / s;
        int   my_e = 0;
        float my_s = 0.f;
        #pragma unroll
        for (int k = 0; k < TOPK; k++) {
            float v; int ei;
            if (p0 >= p1) { v = p0; ei = lane; } else { v = p1; ei = lane + 32; }
            #pragma unroll
            for (int o = 16; o; o >>= 1) {
                float ov = __shfl_xor_sync(0xffffffffu, v, o);
                int   oe = __shfl_xor_sync(0xffffffffu, ei, o);
                if (ov > v || (ov == v && oe < ei)) { v = ov; ei = oe; }
            }
            if (lane == k) { my_e = ei; my_s = v * inv; }
            if (ei < 32)  { if (lane == ei)      p0 = -2.f; }
            else          { if (lane == ei - 32) p1 = -2.f; }
        }
        if (lane < TOPK) {
            const int p = token * TOPK + lane;
            g_eid[p] = my_e;
            g_scr[p] = my_s;
            int slot = atomicAdd(&g_cnt[my_e], 1);
            g_slot[p] = slot;
            if (slot < CAP) g_tok[my_e * CAP + slot] = token;
        }
    }
}

// == 128x128 fp16 MMA mainloop: 128 thr, 4 warps (2m x 2n), 64x64 warp tile ==
// 3-stage cp.async pipeline. Per-thread loads 8 16B-units per operand per
// chunk; unit i = row (r0 + 16i), smem offset offa0 + i*2048 (swizzle-invariant
// because (r & 7) is constant across i).
__device__ __forceinline__ void mainloop(
    uint8_t* sm, uint32_t sbase,
    const __half* const (&aptr)[8],
    const float* bsrc, int64_t bstride,
    uint32_t offa0,
    int wm, int wn, int lane, int NK, float (&acc)[4][8][4])
{
    #pragma unroll
    for (int a = 0; a < 4; a++)
        #pragma unroll
        for (int b = 0; b < 8; b++)
            #pragma unroll
            for (int c = 0; c < 4; c++) acc[a][b][c] = 0.f;

    // prologue: A(0),A(1) cp.async (2 groups); B(0) STS; B(1) -> regs
    #pragma unroll
    for (int s = 0; s < 2; s++) {
        #pragma unroll
        for (int i = 0; i < 8; i++)
            CP16(sbase + s * STAGEB + offa0 + i * 2048, aptr[i] + s * 64);
        CPCOMMIT();
    }
    #pragma unroll
    for (int i = 0; i < 8; i++) {
        float4 u = *(const float4*)(bsrc + i * bstride);
        float4 v = *(const float4*)(bsrc + i * bstride + 4);
        *(uint4*)(sm + 16384 + offa0 + i * 2048) = pack8(u, v);
    }
    uint4 vb[8];
    #pragma unroll
    for (int i = 0; i < 8; i++) {
        float4 u = *(const float4*)(bsrc + i * bstride + 64);
        float4 v = *(const float4*)(bsrc + i * bstride + 68);
        vb[i] = pack8(u, v);
    }

    uint32_t cur = 0, nxt = STAGEB, nx2 = 2 * STAGEB;
    #pragma unroll 1
    for (int j = 0; j < NK; j++) {
        CPWAIT1();
        __syncthreads();
        // A(j+2) cp.async into stage nx2
        if (j + 2 < NK) {
            #pragma unroll
            for (int i = 0; i < 8; i++)
                CP16(sbase + nx2 + offa0 + i * 2048, aptr[i] + (j + 2) * 64);
        }
        CPCOMMIT();
        // STS B(j+1) (pre-packed)
        if (j + 1 < NK) {
            #pragma unroll
            for (int i = 0; i < 8; i++)
                *(uint4*)(sm + nxt + 16384 + offa0 + i * 2048) = vb[i];
        }
        // LDG+pack B(j+2)
        if (j + 2 < NK) {
            #pragma unroll
            for (int i = 0; i < 8; i++) {
                float4 u = *(const float4*)(bsrc + i * bstride + (j + 2) * 64);
                float4 v = *(const float4*)(bsrc + i * bstride + (j + 2) * 64 + 4);
                vb[i] = pack8(u, v);
            }
        }
        // MMA(j)
        const uint32_t sA = sbase + cur, sB = sA + 16384;
        #pragma unroll
        for (int ks = 0; ks < 4; ks++) {
            uint32_t af[4][4], bf[4][4];
            #pragma unroll
            for (int n2 = 0; n2 < 4; n2++) {
                int row = wn * 64 + n2 * 16 + ((lane >> 4) << 3) + (lane & 7);
                int byt = ks * 32 + (((lane >> 3) & 1) << 4);
                ldsm4(bf[n2], sB + row * 128 + (byt ^ ((row & 7) << 4)));
            }
            #pragma unroll
            for (int mt = 0; mt < 4; mt++) {
                int row = wm * 64 + mt * 16 + (lane & 15);
                int byt = ks * 32 + ((lane >> 4) << 4);
                ldsm4(af[mt], sA + row * 128 + (byt ^ ((row & 7) << 4)));
            }
            #pragma unroll
            for (int mt = 0; mt < 4; mt++)
                #pragma unroll
                for (int nt = 0; nt < 8; nt++)
                    mma16816(acc[mt][nt], af[mt], &bf[nt >> 1][(nt & 1) * 2]);
        }
        uint32_t t = cur; cur = nxt; nxt = nx2; nx2 = t;
    }
}

// ---------------- K3: gate/up GEMM + SwiGLU ----------------------------------
__global__ __launch_bounds__(128, 2) void k_gateup_mma(const float* __restrict__ wg,
                                                       const float* __restrict__ wu) {
    extern __shared__ __align__(1024) uint8_t sm[];
    const int e = blockIdx.z;
    int nrows = g_cnt[e]; if (nrows > CAP) nrows = CAP;
    const int row0 = blockIdx.y * 128;
    if (row0 >= nrows) return;
    const int f0 = blockIdx.x * 64;

    const int tid = threadIdx.x;
    const int wid = tid >> 5, lane = tid & 31;
    const int wm = wid & 1, wn = wid >> 1;
    const uint32_t sbase = smem_u32(sm);

    const int r0 = tid >> 3, c = tid & 7;            // r0: 0..15
    const uint32_t offa0 = r0 * 128 + ((c * 16) ^ ((r0 & 7) << 4));

    // A: 8 gathered token rows (r0 + 16i)
    const __half* aptr[8];
    #pragma unroll
    for (int i = 0; i < 8; i++) {
        int rr = row0 + r0 + 16 * i;
        int tok = g_tok[e * CAP + (rr < nrows ? rr : 0)];
        aptr[i] = g_xh + (size_t)tok * DIM + c * 8;
    }
    // B row r = r0 + 16i: t8 = (r0>>3) + 2i -> parity fixed; fr = f0 + 8i + (r0&7)
    const int t8_0 = r0 >> 3, w8 = r0 & 7;
    const float* wb = (t8_0 & 1) ? wu : wg;
    const float* bsrc = wb + ((size_t)e * FFN_ + f0 + w8) * DIM + c * 8;
    const int64_t bstride = (int64_t)8 * DIM;

    float acc[4][8][4];
    mainloop(sm, sbase, aptr, bsrc, bstride, offa0, wm, wn, lane, DIM / 64, acc);

    // epilogue: global n-tile g = wn*8 + nt; pairs (even=gate, odd=up) share
    // f-block (g>>1). nt parity == g parity.
    const int qrow = lane >> 2, qcol = (lane & 3) * 2;
    #pragma unroll
    for (int mt = 0; mt < 4; mt++) {
        int mbase = row0 + wm * 64 + mt * 16;
        #pragma unroll
        for (int p = 0; p < 4; p++) {
            int fbase = f0 + (wn * 4 + p) * 8 + qcol;
            float* gA = acc[mt][2 * p];
            float* uA = acc[mt][2 * p + 1];
            int ra = mbase + qrow, rb = mbase + qrow + 8;
            if (ra < nrows) {
                __half2 h = __floats2half2_rn(silu_(gA[0]) * uA[0], silu_(gA[1]) * uA[1]);
                *(__half2*)&g_h[((size_t)e * CAP + ra) * FFN_ + fbase] = h;
            }
            if (rb < nrows) {
                __half2 h = __floats2half2_rn(silu_(gA[2]) * uA[2], silu_(gA[3]) * uA[3]);
                *(__half2*)&g_h[((size_t)e * CAP + rb) * FFN_ + fbase] = h;
            }
        }
    }
}

// ---------------- K4: down GEMM ----------------------------------------------
__global__ __launch_bounds__(128, 2) void k_down_mma(const float* __restrict__ wd) {
    extern __shared__ __align__(1024) uint8_t sm[];
    const int e = blockIdx.z;
    int nrows = g_cnt[e]; if (nrows > CAP) nrows = CAP;
    const int row0 = blockIdx.y * 128;
    if (row0 >= nrows) return;
    const int d0 = blockIdx.x * 128;

    const int tid = threadIdx.x;
    const int wid = tid >> 5, lane = tid & 31;
    const int wm = wid & 1, wn = wid >> 1;
    const uint32_t sbase = smem_u32(sm);

    const int r0 = tid >> 3, c = tid & 7;
    const uint32_t offa0 = r0 * 128 + ((c * 16) ^ ((r0 & 7) << 4));

    const __half* abase = g_h + ((size_t)e * CAP + row0 + r0) * FFN_ + c * 8;
    const __half* aptr[8];
    #pragma unroll
    for (int i = 0; i < 8; i++) aptr[i] = abase + (size_t)(16 * i) * FFN_;

    const float* bsrc = wd + ((size_t)e * DIM + d0 + r0) * FFN_ + c * 8;
    const int64_t bstride = (int64_t)16 * FFN_;

    float acc[4][8][4];
    mainloop(sm, sbase, aptr, bsrc, bstride, offa0, wm, wn, lane, FFN_ / 64, acc);

    const int qrow = lane >> 2, qcol = (lane & 3) * 2;
    #pragma unroll
    for (int mt = 0; mt < 4; mt++) {
        int mbase = row0 + wm * 64 + mt * 16;
        #pragma unroll
        for (int nt = 0; nt < 8; nt++) {
            int dcol = d0 + wn * 64 + nt * 8 + qcol;
            int ra = mbase + qrow, rb = mbase + qrow + 8;
            if (ra < nrows) {
                __half2 h = __floats2half2_rn(acc[mt][nt][0], acc[mt][nt][1]);
                *(__half2*)&g_y[((size_t)e * CAP + ra) * DIM + dcol] = h;
            }
            if (rb < nrows) {
                __half2 h = __floats2half2_rn(acc[mt][nt][2], acc[mt][nt][3]);
                *(__half2*)&g_y[((size_t)e * CAP + rb) * DIM + dcol] = h;
            }
        }
    }
}

// ---------------- K5: weighted combine (fp16 y, fp32 acc) --------------------
__global__ __launch_bounds__(256) void k_combine(float* __restrict__ out) {
    const int t = blockIdx.x;
    const int tid = threadIdx.x;
    float acc[8];
    #pragma unroll
    for (int i = 0; i < 8; i++) acc[i] = 0.f;
    #pragma unroll
    for (int k = 0; k < TOPK; k++) {
        const int p = t * TOPK + k;
        const int e = g_eid[p];
        const int s = g_slot[p];
        if (s >= CAP) continue;
        const float sc = g_scr[p];
        const uint4* yr = (const uint4*)&g_y[((size_t)e * CAP + s) * DIM];
        uint4 v = yr[tid];
        uint32_t w[4] = {v.x, v.y, v.z, v.w};
        #pragma unroll
        for (int i = 0; i < 4; i++) {
            float2 f = __half22float2(*(__half2*)&w[i]);
            acc[2*i]   += sc * f.x;
            acc[2*i+1] += sc * f.y;
        }
    }
    float* op = out + (size_t)t * DIM + tid * 8;
    *(float4*)op       = make_float4(acc[0], acc[1], acc[2], acc[3]);
    *(float4*)(op + 4) = make_float4(acc[4], acc[5], acc[6], acc[7]);
}

// ---------------- launch -----------------------------------------------------
extern "C" void kernel_launch(void* const* d_in, const int* in_sizes, int n_in,
                              void* d_out, int out_size) {
    (void)in_sizes; (void)n_in; (void)out_size;
    const float* x      = (const float*)d_in[0];
    const float* gate_w = (const float*)d_in[1];
    const float* w_gate = (const float*)d_in[2];
    const float* w_up   = (const float*)d_in[3];
    const float* w_down = (const float*)d_in[4];
    float* out          = (float*)d_out;

    cudaFuncSetAttribute(k_gateup_mma, cudaFuncAttributeMaxDynamicSharedMemorySize, SMEM_DYN);
    cudaFuncSetAttribute(k_down_mma,   cudaFuncAttributeMaxDynamicSharedMemorySize, SMEM_DYN);

    k_zero<<<1, 64>>>();
    k_gate<<<NT / 4, 256>>>(x, gate_w);
    k_gateup_mma<<<dim3(FFN_ / 64, CAP / 128, NE), 128, SMEM_DYN>>>(w_gate, w_up);
    k_down_mma<<<dim3(DIM / 128, CAP / 128, NE), 128, SMEM_DYN>>>(w_down);
    k_combine<<<NT, 256>>>(out);
}